// round 8
// baseline (speedup 1.0000x reference)
#include <cuda_runtime.h>

// ---------------------------------------------------------------------------
// Problem constants
// ---------------------------------------------------------------------------
constexpr int Bb  = 2048;
constexpr int Nn  = 8;
constexpr int Tt  = 20;
constexpr int Mm  = Bb * Nn;        // 16384 sequences
constexpr int HS  = 128;
constexpr int G3  = 3 * HS;         // 384
constexpr int RT  = Mm * Tt;        // 327680 rows (m*T + t)
constexpr int WTP = 388;            // weight tile pitch (16B-aligned, conflict-free)
constexpr int DPP = 132;            // dup tile pitch (64 k dup -> 128 floats + 4 pad)
constexpr int OUT0 = Mm * 64;       // first output section ("out")

// Scratch as device globals (no runtime allocation allowed)
__device__ float g_gi[(size_t)RT * G3];   // 503 MB input-gate preactivations
__device__ float g_ys[(size_t)RT * HS];   // 168 MB layer outputs (reused per layer)

typedef unsigned long long ULL;

// packed f32x2 FMA (full fp32 rate on sm_103a requires fma.rn.f32x2)
__device__ __forceinline__ void fma2(ULL& d, ULL a, ULL b) {
    asm("fma.rn.f32x2 %0, %1, %2, %0;" : "+l"(d) : "l"(a), "l"(b));
}
__device__ __forceinline__ float2 unpk(ULL v) {
    float2 f; asm("mov.b64 {%0, %1}, %2;" : "=f"(f.x), "=f"(f.y) : "l"(v)); return f;
}
__device__ __forceinline__ float sigm(float x) { return 1.0f / (1.0f + __expf(-x)); }
__device__ __forceinline__ float tanh_(float x) { return 1.0f - 2.0f / (__expf(2.0f * x) + 1.0f); }

// ---------------------------------------------------------------------------
// gi GEMM:  gi[r,:] = xs[r,:] @ Wih^T + bih        (r = m*T + t)
// 512 threads, 64 rows/CTA. Thread: 8 rows x 1 col-pair x 3 gates = 24 accs.
// 16 warps = 4/SMSP. x tile dup over a 64-k chunk ([row][2k]) -> the (h,h)
// f32x2 operand is one broadcast LDS.128, no movs. Full weights in smem.
// Per k-pair/SM: 320 LDS wf < 384 FMA cyc -> fma-bound.
// K=64 fuses the embedding; K=128 reads g_ys.
// ---------------------------------------------------------------------------
template <int K>
__global__ __launch_bounds__(512) void gi_gemm(
    const float* __restrict__ Wih, const float* __restrict__ bih,
    const float* __restrict__ x,   const float* __restrict__ pea,
    const float* __restrict__ pet, const float* __restrict__ embW,
    const float* __restrict__ embB)
{
    extern __shared__ float sm[];
    float* Wt = sm;                 // [K][WTP]
    float* xT = sm + K * WTP;       // [64][DPP]  dup over current 64-k chunk

    int tid = threadIdx.x;

    // transpose Wih (G3 x K) -> Wt[k][g]; lanes write consecutive g: conflict-free
    for (int g = tid; g < G3; g += 512) {
        const float* src = Wih + (size_t)g * K;
#pragma unroll 4
        for (int k0 = 0; k0 < K; k0 += 4) {
            float4 w = *(const float4*)(src + k0);
            Wt[(k0 + 0) * WTP + g] = w.x;
            Wt[(k0 + 1) * WTP + g] = w.y;
            Wt[(k0 + 2) * WTP + g] = w.z;
            Wt[(k0 + 3) * WTP + g] = w.w;
        }
    }

    int rg = tid >> 6;              // row-group 0..7 (8 rows each)
    int pp = tid & 63;              // column-pair 0..63
    int c2 = 2 * pp;
    int r0 = rg * 8;
    int row0 = blockIdx.x * 64;

    ULL acc[3][8];
#pragma unroll
    for (int g = 0; g < 3; ++g)
#pragma unroll
        for (int j = 0; j < 8; ++j) acc[g][j] = 0ULL;

    constexpr int NCH = K / 64;
    for (int ch = 0; ch < NCH; ++ch) {
        __syncthreads();   // Wt ready / previous chunk's xT reads done
        // fill xT (duplicated): 64 rows x 16 float4 reads
        for (int idx = tid; idx < 64 * 16; idx += 512) {
            int r = idx >> 4, kq = idx & 15;
            float4 v;
            if (K == 64) {
                // fused embedding: v_e = relu(emb_b + (x0+pe)W[e,0] + (x1+pe)W[e,1])
                int row = row0 + r;
                int t = row % Tt;
                int n = (row / Tt) & 7;
                float pe = __ldg(pet + t) + __ldg(pea + n);
                float2 xv = *(const float2*)(x + (size_t)row * 2);
                float x0 = xv.x + pe, x1 = xv.y + pe;
                float4 w0 = __ldg((const float4*)(embW + 8 * kq));
                float4 w1 = __ldg((const float4*)(embW + 8 * kq + 4));
                float4 b4 = __ldg((const float4*)(embB + 4 * kq));
                v.x = fmaxf(fmaf(x0, w0.x, fmaf(x1, w0.y, b4.x)), 0.0f);
                v.y = fmaxf(fmaf(x0, w0.z, fmaf(x1, w0.w, b4.y)), 0.0f);
                v.z = fmaxf(fmaf(x0, w1.x, fmaf(x1, w1.y, b4.z)), 0.0f);
                v.w = fmaxf(fmaf(x0, w1.z, fmaf(x1, w1.w, b4.w)), 0.0f);
            } else {
                v = *(const float4*)(g_ys + (size_t)(row0 + r) * K + ch * 64 + 4 * kq);
            }
            float* d = xT + r * DPP + 8 * kq;
            *(float4*)(d)     = make_float4(v.x, v.x, v.y, v.y);
            *(float4*)(d + 4) = make_float4(v.z, v.z, v.w, v.w);
        }
        __syncthreads();

#pragma unroll 2
        for (int k2 = 0; k2 < 32; ++k2) {           // k-pairs within chunk
            const float* wb = Wt + (size_t)(ch * 64 + 2 * k2) * WTP + c2;
            ULL w0r = *(const ULL*)(wb);
            ULL w0z = *(const ULL*)(wb + 128);
            ULL w0n = *(const ULL*)(wb + 256);
            ULL w1r = *(const ULL*)(wb + WTP);
            ULL w1z = *(const ULL*)(wb + WTP + 128);
            ULL w1n = *(const ULL*)(wb + WTP + 256);
            const float* hb = xT + r0 * DPP + 4 * k2;
#pragma unroll
            for (int j = 0; j < 8; ++j) {
                ulonglong2 h = *(const ulonglong2*)(hb + j * DPP);  // (hk hk | hk1 hk1)
                fma2(acc[0][j], h.x, w0r); fma2(acc[1][j], h.x, w0z); fma2(acc[2][j], h.x, w0n);
                fma2(acc[0][j], h.y, w1r); fma2(acc[1][j], h.y, w1z); fma2(acc[2][j], h.y, w1n);
            }
        }
    }

    // epilogue: bias + coalesced STG.64
#pragma unroll
    for (int g = 0; g < 3; ++g) {
        float2 b2 = *(const float2*)(bih + g * 128 + c2);
#pragma unroll
        for (int j = 0; j < 8; ++j) {
            float2 p = unpk(acc[g][j]);
            p.x += b2.x; p.y += b2.y;
            *(float2*)(g_gi + (size_t)(row0 + r0 + j) * G3 + g * 128 + c2) = p;
        }
    }
}

// ---------------------------------------------------------------------------
// GRU recurrent scan for one layer.
// 256 CTAs x 512 threads x 64 rows; all 20 steps on-chip. 16 warps = 4/SMSP.
// smem: Whh^T [128][WTP] fp32 + ONE chunk-swapped dup h buffer [64][DPP]:
//   the buffer holds the dup form of 64 h-columns at a time; owners of
//   h-cols [0,64) refill it at the end of each step (chunk0), owners of
//   [64,128) refill it between the two half-k loops (chunk1).
// Thread: 8 rows x 1 col-pair x 3 gates. Per k-pair/SM: 320 wf < 384 FMA cyc.
// ---------------------------------------------------------------------------
__global__ __launch_bounds__(512) void scan_kernel(
    const float* __restrict__ Whh, const float* __restrict__ bhh,
    float* __restrict__ hid)
{
    extern __shared__ float sm[];
    float* Wt = sm;              // [128][WTP]
    float* hB = sm + HS * WTP;   // [64][DPP]  dup buffer (one 64-k chunk)

    int tid = threadIdx.x;
    for (int g = tid; g < G3; g += 512) {
        const float* src = Whh + (size_t)g * HS;
#pragma unroll 4
        for (int k0 = 0; k0 < HS; k0 += 4) {
            float4 w = *(const float4*)(src + k0);
            Wt[(k0 + 0) * WTP + g] = w.x;
            Wt[(k0 + 1) * WTP + g] = w.y;
            Wt[(k0 + 2) * WTP + g] = w.z;
            Wt[(k0 + 3) * WTP + g] = w.w;
        }
    }
    for (int i = tid; i < 64 * DPP; i += 512) hB[i] = 0.0f;   // chunk0 of h0 = 0

    int rg = tid >> 6;           // row-group 0..7 (8 rows each)
    int pp = tid & 63;           // column-pair 0..63 (h-cols c2, c2+1)
    int c2 = 2 * pp;
    int r0 = rg * 8;
    int m0 = blockIdx.x * 64;

    const float2 bR = *(const float2*)(bhh + c2);
    const float2 bZ = *(const float2*)(bhh + 128 + c2);
    const float2 bN = *(const float2*)(bhh + 256 + c2);

    float2 hreg[8];
#pragma unroll
    for (int j = 0; j < 8; ++j) hreg[j] = make_float2(0.0f, 0.0f);

    __syncthreads();

    for (int t = 0; t < Tt; ++t) {
        ULL aR[8], aZ[8], aN[8];
#pragma unroll
        for (int j = 0; j < 8; ++j) { aR[j] = 0ULL; aZ[j] = 0ULL; aN[j] = 0ULL; }

        // ---- chunk 0: k in [0,64), buffer holds dup h[0:64) ----
#pragma unroll 2
        for (int k2 = 0; k2 < 32; ++k2) {
            const float* wb = Wt + (size_t)(2 * k2) * WTP + c2;
            ULL w0r = *(const ULL*)(wb);
            ULL w0z = *(const ULL*)(wb + 128);
            ULL w0n = *(const ULL*)(wb + 256);
            ULL w1r = *(const ULL*)(wb + WTP);
            ULL w1z = *(const ULL*)(wb + WTP + 128);
            ULL w1n = *(const ULL*)(wb + WTP + 256);
            const float* hb = hB + r0 * DPP + 4 * k2;
#pragma unroll
            for (int j = 0; j < 8; ++j) {
                ulonglong2 h = *(const ulonglong2*)(hb + j * DPP);
                fma2(aR[j], h.x, w0r); fma2(aZ[j], h.x, w0z); fma2(aN[j], h.x, w0n);
                fma2(aR[j], h.y, w1r); fma2(aZ[j], h.y, w1z); fma2(aN[j], h.y, w1n);
            }
        }
        __syncthreads();   // B1: chunk0 reads done

        // owners of h-cols [64,128) write dup chunk1 into the buffer
        if (pp >= 32) {
            int off = 4 * pp - 128;          // float offset in row
#pragma unroll
            for (int j = 0; j < 8; ++j)
                *(float4*)(hB + (r0 + j) * DPP + off) =
                    make_float4(hreg[j].x, hreg[j].x, hreg[j].y, hreg[j].y);
        }
        __syncthreads();   // B2: chunk1 written

        // ---- chunk 1: k in [64,128) ----
#pragma unroll 2
        for (int k2 = 0; k2 < 32; ++k2) {
            const float* wb = Wt + (size_t)(64 + 2 * k2) * WTP + c2;
            ULL w0r = *(const ULL*)(wb);
            ULL w0z = *(const ULL*)(wb + 128);
            ULL w0n = *(const ULL*)(wb + 256);
            ULL w1r = *(const ULL*)(wb + WTP);
            ULL w1z = *(const ULL*)(wb + WTP + 128);
            ULL w1n = *(const ULL*)(wb + WTP + 256);
            const float* hb = hB + r0 * DPP + 4 * k2;
#pragma unroll
            for (int j = 0; j < 8; ++j) {
                ulonglong2 h = *(const ulonglong2*)(hb + j * DPP);
                fma2(aR[j], h.x, w0r); fma2(aZ[j], h.x, w0z); fma2(aN[j], h.x, w0n);
                fma2(aR[j], h.y, w1r); fma2(aZ[j], h.y, w1z); fma2(aN[j], h.y, w1n);
            }
        }
        __syncthreads();   // B3: chunk1 reads done

        // ---- gates + state update ----
#pragma unroll
        for (int j = 0; j < 8; ++j) {
            size_t rbase = (size_t)(m0 + r0 + j) * Tt + t;
            const float* gp = g_gi + rbase * G3;
            float2 giR = *(const float2*)(gp + c2);
            float2 giZ = *(const float2*)(gp + 128 + c2);
            float2 giN = *(const float2*)(gp + 256 + c2);
            float2 ghR = unpk(aR[j]), ghZ = unpk(aZ[j]), ghN = unpk(aN[j]);
            float rv0 = sigm(giR.x + ghR.x + bR.x);
            float rv1 = sigm(giR.y + ghR.y + bR.y);
            float zv0 = sigm(giZ.x + ghZ.x + bZ.x);
            float zv1 = sigm(giZ.y + ghZ.y + bZ.y);
            float nv0 = tanh_(giN.x + rv0 * (ghN.x + bN.x));
            float nv1 = tanh_(giN.y + rv1 * (ghN.y + bN.y));
            float hn0 = (1.0f - zv0) * nv0 + zv0 * hreg[j].x;
            float hn1 = (1.0f - zv1) * nv1 + zv1 * hreg[j].y;
            hreg[j] = make_float2(hn0, hn1);
            *(float2*)(g_ys + rbase * HS + c2) = hreg[j];
        }
        // owners of h-cols [0,64) write dup chunk0 for the next step
        if (pp < 32) {
            int off = 4 * pp;
#pragma unroll
            for (int j = 0; j < 8; ++j)
                *(float4*)(hB + (r0 + j) * DPP + off) =
                    make_float4(hreg[j].x, hreg[j].x, hreg[j].y, hreg[j].y);
        }
        __syncthreads();   // B4: chunk0 ready for next step
    }

    // hidden output: final h of rows with m % 8 == 7 -> row j == 7 in each group
    int b = (m0 + r0 + 7) >> 3;
    *(float2*)(hid + (size_t)b * HS + c2) = hreg[7];
}

// ---------------------------------------------------------------------------
// Output projection  out[m, e] = ys_last[m, :] @ out_W[e, :] + out_b[e]
// ---------------------------------------------------------------------------
__global__ __launch_bounds__(256) void out_kernel(
    const float* __restrict__ oW, const float* __restrict__ ob,
    float* __restrict__ out)
{
    __shared__ float sW[128 * 64];   // transposed [k][e]
    int tid = threadIdx.x;
    for (int idx = tid; idx < 64 * 128; idx += 256) {
        int e = idx >> 7, k = idx & 127;
        sW[k * 64 + e] = oW[idx];
    }
    __syncthreads();
    int gid = blockIdx.x * 256 + tid;       // gid = m*64 + e
    int e = gid & 63;
    int m = gid >> 6;
    const float* ys = g_ys + ((size_t)m * Tt + (Tt - 1)) * HS;
    float acc = ob[e];
#pragma unroll 8
    for (int k = 0; k < 128; ++k) acc = fmaf(ys[k], sW[k * 64 + e], acc);
    out[gid] = acc;
}

// ---------------------------------------------------------------------------
// Launch
// ---------------------------------------------------------------------------
extern "C" void kernel_launch(void* const* d_in, const int* in_sizes, int n_in,
                              void* d_out, int out_size) {
    const float* x    = (const float*)d_in[0];
    const float* pea  = (const float*)d_in[1];
    const float* pet  = (const float*)d_in[2];
    const float* embW = (const float*)d_in[3];
    const float* embB = (const float*)d_in[4];
    const float* Wih0 = (const float*)d_in[5];
    const float* WihR = (const float*)d_in[6];   // (2, 384, 128)
    const float* Whh  = (const float*)d_in[7];   // (3, 384, 128)
    const float* bih  = (const float*)d_in[8];   // (3, 384)
    const float* bhh  = (const float*)d_in[9];   // (3, 384)
    const float* outW = (const float*)d_in[10];  // (64, 128)
    const float* outB = (const float*)d_in[11];

    float* out = (float*)d_out;                  // [Mm*64]
    float* hid = out + OUT0;                     // [3][Bb][HS]

    const int smem64   = 64  * WTP * 4 + 64 * DPP * 4;  //  99328 + 33792 = 133120
    const int smem128  = 128 * WTP * 4 + 64 * DPP * 4;  // 198656 + 33792 = 232448
    const int smemScan = smem128;                       // 232448 (= 227 KB cap)
    cudaFuncSetAttribute(gi_gemm<64>,  cudaFuncAttributeMaxDynamicSharedMemorySize, smem64);
    cudaFuncSetAttribute(gi_gemm<128>, cudaFuncAttributeMaxDynamicSharedMemorySize, smem128);
    cudaFuncSetAttribute(scan_kernel,  cudaFuncAttributeMaxDynamicSharedMemorySize, smemScan);

    // layer 0 (embedding fused into the gi x-tile fill)
    gi_gemm<64><<<RT / 64, 512, smem64>>>(Wih0, bih, x, pea, pet, embW, embB);
    scan_kernel<<<Mm / 64, 512, smemScan>>>(Whh, bhh, hid);
    // layer 1
    gi_gemm<128><<<RT / 64, 512, smem128>>>(WihR, bih + G3, x, pea, pet, embW, embB);
    scan_kernel<<<Mm / 64, 512, smemScan>>>(Whh + (size_t)G3 * HS, bhh + G3,
                                            hid + (size_t)Bb * HS);
    // layer 2
    gi_gemm<128><<<RT / 64, 512, smem128>>>(WihR + (size_t)G3 * HS, bih + 2 * G3,
                                            x, pea, pet, embW, embB);
    scan_kernel<<<Mm / 64, 512, smemScan>>>(Whh + (size_t)2 * G3 * HS, bhh + 2 * G3,
                                            hid + (size_t)2 * Bb * HS);

    out_kernel<<<(Mm * 64) / 256, 256>>>(outW, outB, out);
}